// round 1
// baseline (speedup 1.0000x reference)
#include <cuda_runtime.h>
#include <cuda_bf16.h>
#include <cfloat>
#include <cstdint>

// Problem constants
#define NUM_EMBED 512
#define EMBED_DIM 64
#define N_TOKENS  131072            // 32 * 64 * 64
#define HW        4096              // 64*64
#define DECAY     0.99f
#define ONE_MINUS_DECAY 0.01f
#define EPS       1e-5f
#define COMMIT_COST 0.25f

// Output layout (float elements), tuple order:
// (loss[1], out[8388608], perplexity[1], encodings[131072*512],
//  new_embedding[512*64], cluster[512], new_ema_w[512*64])
#define OFF_LOSS   0
#define OFF_OUT    1
#define OFF_PERP   8388609
#define OFF_ENC    8388610
#define OFF_NEMB   75497474ll
#define OFF_CLUST  75530242ll
#define OFF_EMAW   75530754ll

// Scratch (no allocations allowed -> device globals)
__device__ float  g_counts[NUM_EMBED];
__device__ float  g_dw[NUM_EMBED * EMBED_DIM];
__device__ float  g_en2[NUM_EMBED];
__device__ float  g_loss;

typedef unsigned long long ull;

// ---- f32x2 packed-math helpers (sm_100+ only; PTX-only, ptxas won't auto-fuse) ----
__device__ __forceinline__ ull fma2(ull a, ull b, ull c) {
    ull d;
    asm("fma.rn.f32x2 %0, %1, %2, %3;" : "=l"(d) : "l"(a), "l"(b), "l"(c));
    return d;
}
__device__ __forceinline__ ull add2(ull a, ull b) {
    ull d;
    asm("add.rn.f32x2 %0, %1, %2;" : "=l"(d) : "l"(a), "l"(b));
    return d;
}
__device__ __forceinline__ ull pack2(float lo, float hi) {
    ull d;
    asm("mov.b64 %0, {%1, %2};" : "=l"(d) : "f"(lo), "f"(hi));
    return d;
}
__device__ __forceinline__ float2 unpack2(ull v) {
    float2 r;
    asm("mov.b64 {%0, %1}, %2;" : "=f"(r.x), "=f"(r.y) : "l"(v));
    return r;
}
__device__ __forceinline__ void lds_v2_u64(ull& a, ull& b, unsigned addr) {
    asm("ld.shared.v2.u64 {%0, %1}, [%2];" : "=l"(a), "=l"(b) : "r"(addr));
}

// ============================================================
// Phase 0: zero scratch + precompute ||e||^2. One block, 512 threads.
// ============================================================
__global__ void vq_phase0(const float* __restrict__ emb) {
    int tid = threadIdx.x;
    g_counts[tid] = 0.0f;
    if (tid == 0) g_loss = 0.0f;
    // ||e||^2
    const float2* ep = reinterpret_cast<const float2*>(emb + tid * EMBED_DIM);
    float s = 0.0f;
#pragma unroll
    for (int j = 0; j < 32; ++j) {
        float2 v = ep[j];
        s += v.x * v.x + v.y * v.y;
    }
    g_en2[tid] = s;
    // zero dw
    for (int i = tid; i < NUM_EMBED * EMBED_DIM; i += 512) g_dw[i] = 0.0f;
}

// ============================================================
// Phase 1: fused argmin + quantize + out + encodings + counts + dw + loss.
// 512 blocks x 128 threads; each thread owns 2 tokens (full x row in regs,
// packed as f32x2 over dim pairs). Distances via packed FFMA2, codes chunked
// through shared memory (broadcast LDS.128).
// ============================================================
__global__ void __launch_bounds__(128, 2)
vq_phase1(const float* __restrict__ x,
          const float* __restrict__ emb,
          float* __restrict__ dout) {
    __shared__ float es[128 * EMBED_DIM];   // 32 KB code chunk
    __shared__ float en2s[128];
    __shared__ float red[128];

    const int tid   = threadIdx.x;
    const int tbase = blockIdx.x << 8;          // 256 tokens per block
    const int n     = tbase >> 12;              // batch index
    const int hw0   = (tbase & 4095) + tid;     // token A spatial pos
    // token A = tbase + tid ; token B = tbase + 128 + tid

    const float* xp = x + ((size_t)n << 18) + hw0;   // n*64*4096 + hw0

    // Load both tokens' 64 features into registers, packed over dim pairs.
    ull xA[32], xB[32];
#pragma unroll
    for (int j = 0; j < 32; ++j) {
        float a0 = xp[(2 * j) << 12];
        float a1 = xp[(2 * j + 1) << 12];
        xA[j] = pack2(a0, a1);
        float b0 = xp[((2 * j) << 12) + 128];
        float b1 = xp[((2 * j + 1) << 12) + 128];
        xB[j] = pack2(b0, b1);
    }

    const unsigned sbase = (unsigned)__cvta_generic_to_shared(es);

    float bestA = FLT_MAX, bestB = FLT_MAX;
    int biA = 0, biB = 0;

    for (int ch = 0; ch < 4; ++ch) {
        __syncthreads();
        {   // cooperative load of 128 codes (8192 floats) + their norms
            const float4* src = reinterpret_cast<const float4*>(emb) + ch * 2048;
            float4* dst = reinterpret_cast<float4*>(es);
#pragma unroll
            for (int i = 0; i < 16; ++i) dst[tid + i * 128] = src[tid + i * 128];
            if (tid < 128) en2s[tid] = g_en2[ch * 128 + tid];
        }
        __syncthreads();

#pragma unroll 2
        for (int e = 0; e < 128; ++e) {
            unsigned ad = sbase + e * (EMBED_DIM * 4);
            ull a0 = 0, a1 = 0, b0 = 0, b1 = 0;
#pragma unroll
            for (int j = 0; j < 16; ++j) {
                ull e01, e23;
                lds_v2_u64(e01, e23, ad + j * 16);
                a0 = fma2(xA[2 * j],     e01, a0);
                a1 = fma2(xA[2 * j + 1], e23, a1);
                b0 = fma2(xB[2 * j],     e01, b0);
                b1 = fma2(xB[2 * j + 1], e23, b1);
            }
            float2 sa = unpack2(add2(a0, a1));
            float2 sb = unpack2(add2(b0, b1));
            float dotA = sa.x + sa.y;
            float dotB = sb.x + sb.y;
            float en = en2s[e];
            float dA = fmaf(-2.0f, dotA, en);
            float dB = fmaf(-2.0f, dotB, en);
            int ei = ch * 128 + e;
            bool cA = dA < bestA;
            bestA = cA ? dA : bestA;  biA = cA ? ei : biA;
            bool cB = dB < bestB;
            bestB = cB ? dB : bestB;  biB = cB ? ei : biB;
        }
    }

    // ---- Emit per-token outputs ----
    float lsum = 0.0f;
    float* out_main = dout + OFF_OUT;
    float* out_enc  = dout + OFF_ENC;

    // Token A
    {
        int t = tbase + tid;
        // one-hot row: zero-fill then set (same-thread ordering guarantees 1.0 wins)
        float2* er = reinterpret_cast<float2*>(out_enc + (size_t)t * NUM_EMBED);
        float2 z = make_float2(0.0f, 0.0f);
#pragma unroll 8
        for (int i = 0; i < 256; ++i) er[i] = z;
        out_enc[(size_t)t * NUM_EMBED + biA] = 1.0f;

        atomicAdd(&g_counts[biA], 1.0f);
        const float* q = emb + biA * EMBED_DIM;
        float* op = out_main + ((size_t)n << 18) + hw0;
        float* dwp = g_dw + biA * EMBED_DIM;
#pragma unroll
        for (int j = 0; j < 32; ++j) {
            float2 xv = unpack2(xA[j]);
            float d0 = q[2 * j]     - xv.x;
            float d1 = q[2 * j + 1] - xv.y;
            op[(2 * j) << 12]       = xv.x + d0;
            op[((2 * j + 1) << 12)] = xv.y + d1;
            lsum += d0 * d0 + d1 * d1;
            atomicAdd(dwp + 2 * j,     xv.x);
            atomicAdd(dwp + 2 * j + 1, xv.y);
        }
    }
    // Token B
    {
        int t = tbase + 128 + tid;
        float2* er = reinterpret_cast<float2*>(out_enc + (size_t)t * NUM_EMBED);
        float2 z = make_float2(0.0f, 0.0f);
#pragma unroll 8
        for (int i = 0; i < 256; ++i) er[i] = z;
        out_enc[(size_t)t * NUM_EMBED + biB] = 1.0f;

        atomicAdd(&g_counts[biB], 1.0f);
        const float* q = emb + biB * EMBED_DIM;
        float* op = out_main + ((size_t)n << 18) + hw0 + 128;
        float* dwp = g_dw + biB * EMBED_DIM;
#pragma unroll
        for (int j = 0; j < 32; ++j) {
            float2 xv = unpack2(xB[j]);
            float d0 = q[2 * j]     - xv.x;
            float d1 = q[2 * j + 1] - xv.y;
            op[(2 * j) << 12]       = xv.x + d0;
            op[((2 * j + 1) << 12)] = xv.y + d1;
            lsum += d0 * d0 + d1 * d1;
            atomicAdd(dwp + 2 * j,     xv.x);
            atomicAdd(dwp + 2 * j + 1, xv.y);
        }
    }

    // block-reduce loss partial
    red[tid] = lsum;
    __syncthreads();
#pragma unroll
    for (int o = 64; o > 0; o >>= 1) {
        if (tid < o) red[tid] += red[tid + o];
        __syncthreads();
    }
    if (tid == 0) atomicAdd(&g_loss, red[0]);
}

// ============================================================
// Phase 2: EMA finalize + perplexity + loss. One block, 512 threads.
// ============================================================
__global__ void vq_phase2(const float* __restrict__ ema_cs,
                          const float* __restrict__ ema_w,
                          float* __restrict__ dout) {
    __shared__ float s[512];
    int e = threadIdx.x;

    float cnt = g_counts[e];
    float cl = ema_cs[e] * DECAY + ONE_MINUS_DECAY * cnt;

    // k = sum(cluster)
    s[e] = cl;
    __syncthreads();
    for (int o = 256; o > 0; o >>= 1) {
        if (e < o) s[e] += s[e + o];
        __syncthreads();
    }
    float k = s[0];
    __syncthreads();

    float cls = (cl + EPS) / (k + NUM_EMBED * EPS) * k;
    dout[OFF_CLUST + e] = cls;

    const float2* wp = reinterpret_cast<const float2*>(ema_w + e * EMBED_DIM);
    const float2* dp = reinterpret_cast<const float2*>(g_dw + e * EMBED_DIM);
    float2* ow = reinterpret_cast<float2*>(dout + OFF_EMAW + (size_t)e * EMBED_DIM);
    float2* oe = reinterpret_cast<float2*>(dout + OFF_NEMB + (size_t)e * EMBED_DIM);
#pragma unroll
    for (int j = 0; j < 32; ++j) {
        float2 w = wp[j];
        float2 d = dp[j];
        float w0 = w.x * DECAY + ONE_MINUS_DECAY * d.x;
        float w1 = w.y * DECAY + ONE_MINUS_DECAY * d.y;
        ow[j] = make_float2(w0, w1);
        oe[j] = make_float2(w0 / cls, w1 / cls);
    }

    // perplexity
    float p = cnt * (1.0f / (float)N_TOKENS);
    float t = -p * logf(p + 1e-10f);
    s[e] = t;
    __syncthreads();
    for (int o = 256; o > 0; o >>= 1) {
        if (e < o) s[e] += s[e + o];
        __syncthreads();
    }
    if (e == 0) {
        dout[OFF_PERP] = expf(s[0]);
        dout[OFF_LOSS] = COMMIT_COST * (g_loss / 8388608.0f);
    }
}

// ============================================================
extern "C" void kernel_launch(void* const* d_in, const int* in_sizes, int n_in,
                              void* d_out, int out_size) {
    const float* x      = (const float*)d_in[0];
    const float* emb    = (const float*)d_in[1];
    const float* ema_w  = (const float*)d_in[2];
    const float* ema_cs = (const float*)d_in[3];
    float* dout = (float*)d_out;

    vq_phase0<<<1, 512>>>(emb);
    vq_phase1<<<N_TOKENS / 256, 128>>>(x, emb, dout);
    vq_phase2<<<1, 512>>>(ema_cs, ema_w, dout);
}

// round 2
// speedup vs baseline: 1.2186x; 1.2186x over previous
#include <cuda_runtime.h>
#include <cuda_bf16.h>
#include <cfloat>
#include <cstdint>

// Problem constants
#define NUM_EMBED 512
#define EMBED_DIM 64
#define N_TOKENS  131072            // 32 * 64 * 64
#define DECAY     0.99f
#define ONE_MINUS_DECAY 0.01f
#define EPS       1e-5f
#define COMMIT_COST 0.25f

// Output layout (float elements), tuple order:
// (loss[1], out[8388608], perplexity[1], encodings[131072*512],
//  new_embedding[512*64], cluster[512], new_ema_w[512*64])
#define OFF_LOSS   0
#define OFF_OUT    1
#define OFF_PERP   8388609
#define OFF_ENC    8388610
#define OFF_NEMB   75497474ll
#define OFF_CLUST  75530242ll
#define OFF_EMAW   75530754ll

// Scratch (no allocations allowed -> device globals)
__device__ float  g_counts[NUM_EMBED];
__device__ float  g_dw[NUM_EMBED * EMBED_DIM];
__device__ float  g_en2[NUM_EMBED];
__device__ float  g_loss;

typedef unsigned long long ull;

// ---- f32x2 packed-math helpers (sm_100+; PTX-only, ptxas won't auto-fuse) ----
__device__ __forceinline__ ull fma2(ull a, ull b, ull c) {
    ull d;
    asm("fma.rn.f32x2 %0, %1, %2, %3;" : "=l"(d) : "l"(a), "l"(b), "l"(c));
    return d;
}
__device__ __forceinline__ ull add2(ull a, ull b) {
    ull d;
    asm("add.rn.f32x2 %0, %1, %2;" : "=l"(d) : "l"(a), "l"(b));
    return d;
}
__device__ __forceinline__ ull pack2(float lo, float hi) {
    ull d;
    asm("mov.b64 %0, {%1, %2};" : "=l"(d) : "f"(lo), "f"(hi));
    return d;
}
__device__ __forceinline__ float2 unpack2(ull v) {
    float2 r;
    asm("mov.b64 {%0, %1}, %2;" : "=f"(r.x), "=f"(r.y) : "l"(v));
    return r;
}
__device__ __forceinline__ void lds_v2_u64(ull& a, ull& b, unsigned addr) {
    asm("ld.shared.v2.u64 {%0, %1}, [%2];" : "=l"(a), "=l"(b) : "r"(addr));
}

// ============================================================
// Phase 0: zero scratch + precompute ||e||^2. 64 blocks x 512 threads.
// ============================================================
__global__ void vq_phase0(const float* __restrict__ emb) {
    int tid = threadIdx.x;
    int gid = blockIdx.x * 512 + tid;
    // zero dw: 32768 floats over 64*512 = 32768 threads, one each
    g_dw[gid] = 0.0f;
    if (blockIdx.x == 0) {
        g_counts[tid] = 0.0f;
        if (tid == 0) g_loss = 0.0f;
        // ||e||^2, one code per thread
        const float2* ep = reinterpret_cast<const float2*>(emb + tid * EMBED_DIM);
        float s = 0.0f;
#pragma unroll
        for (int j = 0; j < 32; ++j) {
            float2 v = ep[j];
            s += v.x * v.x + v.y * v.y;
        }
        g_en2[tid] = s;
    }
}

// ============================================================
// Phase 1: fused argmin + quantize + out + encodings + counts + dw + loss.
// 512 blocks x 128 threads; each thread owns 2 tokens.
// ============================================================
__global__ void __launch_bounds__(128, 2)
vq_phase1(const float* __restrict__ x,
          const float* __restrict__ emb,
          float* __restrict__ dout) {
    __shared__ float es[128 * EMBED_DIM];   // 32 KB code chunk
    __shared__ float en2s[128];
    __shared__ float red[128];

    const int tid   = threadIdx.x;
    const int tbase = blockIdx.x << 8;          // 256 tokens per block
    const int n     = tbase >> 12;              // batch index
    const int hw0   = (tbase & 4095) + tid;     // token A spatial pos
    // token A = tbase + tid ; token B = tbase + 128 + tid

    const float* xp = x + ((size_t)n << 18) + hw0;   // n*64*4096 + hw0

    // Load both tokens' 64 features into registers, packed as f32x2 dim pairs.
    ull xA[32], xB[32];
#pragma unroll
    for (int j = 0; j < 32; ++j) {
        float a0 = xp[(2 * j) << 12];
        float a1 = xp[(2 * j + 1) << 12];
        xA[j] = pack2(a0, a1);
        float b0 = xp[((2 * j) << 12) + 128];
        float b1 = xp[((2 * j + 1) << 12) + 128];
        xB[j] = pack2(b0, b1);
    }

    const unsigned sbase = (unsigned)__cvta_generic_to_shared(es);

    float bestA = FLT_MAX, bestB = FLT_MAX;
    int biA = 0, biB = 0;

    for (int ch = 0; ch < 4; ++ch) {
        __syncthreads();
        {   // cooperative load of 128 codes (8192 floats) + their norms
            const float4* src = reinterpret_cast<const float4*>(emb) + ch * 2048;
            float4* dst = reinterpret_cast<float4*>(es);
#pragma unroll
            for (int i = 0; i < 16; ++i) dst[tid + i * 128] = src[tid + i * 128];
            if (tid < 128) en2s[tid] = g_en2[ch * 128 + tid];
        }
        __syncthreads();

#pragma unroll 2
        for (int e = 0; e < 128; ++e) {
            unsigned ad = sbase + e * (EMBED_DIM * 4);
            ull a0 = 0, a1 = 0, b0 = 0, b1 = 0;
#pragma unroll
            for (int j = 0; j < 16; ++j) {
                ull e01, e23;
                lds_v2_u64(e01, e23, ad + j * 16);
                a0 = fma2(xA[2 * j],     e01, a0);
                a1 = fma2(xA[2 * j + 1], e23, a1);
                b0 = fma2(xB[2 * j],     e01, b0);
                b1 = fma2(xB[2 * j + 1], e23, b1);
            }
            float2 sa = unpack2(add2(a0, a1));
            float2 sb = unpack2(add2(b0, b1));
            float dotA = sa.x + sa.y;
            float dotB = sb.x + sb.y;
            float en = en2s[e];
            float dA = fmaf(-2.0f, dotA, en);
            float dB = fmaf(-2.0f, dotB, en);
            int ei = ch * 128 + e;
            bool cA = dA < bestA;
            bestA = cA ? dA : bestA;  biA = cA ? ei : biA;
            bool cB = dB < bestB;
            bestB = cB ? dB : bestB;  biB = cB ? ei : biB;
        }
    }

    // ---- Emit per-token outputs ----
    float* out_main = dout + OFF_OUT;
    float* out_enc  = dout + OFF_ENC;

    // COALESCED zero of this block's 256 contiguous encodings rows (512 KB).
    // NOTE: OFF_ENC is only 8-byte aligned -> float2, not float4.
    {
        float2* ez = reinterpret_cast<float2*>(out_enc + (size_t)tbase * NUM_EMBED);
        float2 z2 = make_float2(0.0f, 0.0f);
#pragma unroll 8
        for (int i = tid; i < 256 * NUM_EMBED / 2; i += 128) ez[i] = z2;
    }
    __syncthreads();
    // scatter the ones (rows already zeroed by the whole block)
    out_enc[(size_t)(tbase + tid)       * NUM_EMBED + biA] = 1.0f;
    out_enc[(size_t)(tbase + 128 + tid) * NUM_EMBED + biB] = 1.0f;

    float lsum = 0.0f;

    // Token A
    {
        atomicAdd(&g_counts[biA], 1.0f);
        const float* q = emb + biA * EMBED_DIM;
        float* op = out_main + ((size_t)n << 18) + hw0;
        float* dwp = g_dw + biA * EMBED_DIM;
#pragma unroll
        for (int j = 0; j < 32; ++j) {
            float2 xv = unpack2(xA[j]);
            float d0 = q[2 * j]     - xv.x;
            float d1 = q[2 * j + 1] - xv.y;
            op[(2 * j) << 12]       = xv.x + d0;
            op[((2 * j + 1) << 12)] = xv.y + d1;
            lsum += d0 * d0 + d1 * d1;
            atomicAdd(dwp + 2 * j,     xv.x);
            atomicAdd(dwp + 2 * j + 1, xv.y);
        }
    }
    // Token B
    {
        atomicAdd(&g_counts[biB], 1.0f);
        const float* q = emb + biB * EMBED_DIM;
        float* op = out_main + ((size_t)n << 18) + hw0 + 128;
        float* dwp = g_dw + biB * EMBED_DIM;
#pragma unroll
        for (int j = 0; j < 32; ++j) {
            float2 xv = unpack2(xB[j]);
            float d0 = q[2 * j]     - xv.x;
            float d1 = q[2 * j + 1] - xv.y;
            op[(2 * j) << 12]       = xv.x + d0;
            op[((2 * j + 1) << 12)] = xv.y + d1;
            lsum += d0 * d0 + d1 * d1;
            atomicAdd(dwp + 2 * j,     xv.x);
            atomicAdd(dwp + 2 * j + 1, xv.y);
        }
    }

    // block-reduce loss partial
    red[tid] = lsum;
    __syncthreads();
#pragma unroll
    for (int o = 64; o > 0; o >>= 1) {
        if (tid < o) red[tid] += red[tid + o];
        __syncthreads();
    }
    if (tid == 0) atomicAdd(&g_loss, red[0]);
}

// ============================================================
// Phase 2: EMA finalize + perplexity + loss. One block, 512 threads.
// ============================================================
__global__ void vq_phase2(const float* __restrict__ ema_cs,
                          const float* __restrict__ ema_w,
                          float* __restrict__ dout) {
    __shared__ float s[512];
    int e = threadIdx.x;

    float cnt = g_counts[e];
    float cl = ema_cs[e] * DECAY + ONE_MINUS_DECAY * cnt;

    // k = sum(cluster)
    s[e] = cl;
    __syncthreads();
    for (int o = 256; o > 0; o >>= 1) {
        if (e < o) s[e] += s[e + o];
        __syncthreads();
    }
    float k = s[0];
    __syncthreads();

    float cls = (cl + EPS) / (k + NUM_EMBED * EPS) * k;
    dout[OFF_CLUST + e] = cls;

    const float2* wp = reinterpret_cast<const float2*>(ema_w + e * EMBED_DIM);
    const float2* dp = reinterpret_cast<const float2*>(g_dw + e * EMBED_DIM);
    float2* ow = reinterpret_cast<float2*>(dout + OFF_EMAW + (size_t)e * EMBED_DIM);
    float2* oe = reinterpret_cast<float2*>(dout + OFF_NEMB + (size_t)e * EMBED_DIM);
#pragma unroll
    for (int j = 0; j < 32; ++j) {
        float2 w = wp[j];
        float2 d = dp[j];
        float w0 = w.x * DECAY + ONE_MINUS_DECAY * d.x;
        float w1 = w.y * DECAY + ONE_MINUS_DECAY * d.y;
        ow[j] = make_float2(w0, w1);
        oe[j] = make_float2(w0 / cls, w1 / cls);
    }

    // perplexity
    float p = cnt * (1.0f / (float)N_TOKENS);
    float t = -p * logf(p + 1e-10f);
    s[e] = t;
    __syncthreads();
    for (int o = 256; o > 0; o >>= 1) {
        if (e < o) s[e] += s[e + o];
        __syncthreads();
    }
    if (e == 0) {
        dout[OFF_PERP] = expf(s[0]);
        dout[OFF_LOSS] = COMMIT_COST * (g_loss / 8388608.0f);
    }
}

// ============================================================
extern "C" void kernel_launch(void* const* d_in, const int* in_sizes, int n_in,
                              void* d_out, int out_size) {
    const float* x      = (const float*)d_in[0];
    const float* emb    = (const float*)d_in[1];
    const float* ema_w  = (const float*)d_in[2];
    const float* ema_cs = (const float*)d_in[3];
    float* dout = (float*)d_out;

    vq_phase0<<<64, 512>>>(emb);
    vq_phase1<<<N_TOKENS / 256, 128>>>(x, emb, dout);
    vq_phase2<<<1, 512>>>(ema_cs, ema_w, dout);
}

// round 3
// speedup vs baseline: 1.3465x; 1.1049x over previous
#include <cuda_runtime.h>
#include <cuda_bf16.h>
#include <cfloat>
#include <cstdint>

// Problem constants
#define NUM_EMBED 512
#define EMBED_DIM 64
#define N_TOKENS  131072            // 32 * 64 * 64
#define DECAY     0.99f
#define ONE_MINUS_DECAY 0.01f
#define EPS       1e-5f
#define COMMIT_COST 0.25f

// Output layout (float elements), tuple order:
// (loss[1], out[8388608], perplexity[1], encodings[131072*512],
//  new_embedding[512*64], cluster[512], new_ema_w[512*64])
#define OFF_LOSS   0
#define OFF_OUT    1
#define OFF_PERP   8388609
#define OFF_ENC    8388610
#define OFF_NEMB   75497474ll
#define OFF_CLUST  75530242ll
#define OFF_EMAW   75530754ll

// Scratch (no allocations allowed -> device globals)
__device__ float              g_counts[NUM_EMBED];
__device__ __align__(16) float g_dw[NUM_EMBED * EMBED_DIM];
__device__ float              g_en2[NUM_EMBED];
__device__ float              g_loss;

typedef unsigned long long ull;

// ---- f32x2 packed-math helpers (sm_100+; PTX-only) ----
__device__ __forceinline__ ull fma2(ull a, ull b, ull c) {
    ull d;
    asm("fma.rn.f32x2 %0, %1, %2, %3;" : "=l"(d) : "l"(a), "l"(b), "l"(c));
    return d;
}
__device__ __forceinline__ ull add2(ull a, ull b) {
    ull d;
    asm("add.rn.f32x2 %0, %1, %2;" : "=l"(d) : "l"(a), "l"(b));
    return d;
}
__device__ __forceinline__ ull pack2(float lo, float hi) {
    ull d;
    asm("mov.b64 %0, {%1, %2};" : "=l"(d) : "f"(lo), "f"(hi));
    return d;
}
__device__ __forceinline__ float2 unpack2(ull v) {
    float2 r;
    asm("mov.b64 {%0, %1}, %2;" : "=f"(r.x), "=f"(r.y) : "l"(v));
    return r;
}
__device__ __forceinline__ void lds_v2_u64(ull& a, ull& b, unsigned addr) {
    asm("ld.shared.v2.u64 {%0, %1}, [%2];" : "=l"(a), "=l"(b) : "r"(addr));
}
__device__ __forceinline__ void red_add_v4(float* p, float a, float b, float c, float d) {
    asm volatile("red.global.add.v4.f32 [%0], {%1,%2,%3,%4};"
                 :: "l"(p), "f"(a), "f"(b), "f"(c), "f"(d) : "memory");
}

// ============================================================
// Phase 0: zero scratch + precompute ||e||^2. 64 blocks x 512 threads.
// ============================================================
__global__ void vq_phase0(const float* __restrict__ emb) {
    int tid = threadIdx.x;
    int gid = blockIdx.x * 512 + tid;
    g_dw[gid] = 0.0f;                     // 32768 floats, one per thread
    if (blockIdx.x == 0) {
        g_counts[tid] = 0.0f;
        if (tid == 0) g_loss = 0.0f;
        const float2* ep = reinterpret_cast<const float2*>(emb + tid * EMBED_DIM);
        float s = 0.0f;
#pragma unroll
        for (int j = 0; j < 32; ++j) {
            float2 v = ep[j];
            s += v.x * v.x + v.y * v.y;
        }
        g_en2[tid] = s;
    }
}

// ============================================================
// Phase 1: fused argmin + quantize + out + encodings + counts + dw + loss.
// Launched twice with tofs = 0 / 65536; 256 blocks x 256 threads,
// one token per thread (64 regs of x data -> good occupancy/latency hiding).
// ============================================================
__global__ void __launch_bounds__(256, 2)
vq_phase1(const float* __restrict__ x,
          const float* __restrict__ emb,
          float* __restrict__ dout,
          int tofs) {
    __shared__ float es[128 * EMBED_DIM];   // 32 KB code chunk
    __shared__ float en2s[128];
    __shared__ float red[256];

    const int tid   = threadIdx.x;
    const int tbase = tofs + (blockIdx.x << 8);   // 256 tokens per block
    const int n     = tbase >> 12;                // batch index
    const int hw    = (tbase & 4095) + tid;       // spatial pos of this token

    const float* xp = x + ((size_t)n << 18) + hw; // n*64*4096 + hw

    // Load this token's 64 features, packed as f32x2 dim pairs.
    ull xv[32];
#pragma unroll
    for (int j = 0; j < 32; ++j)
        xv[j] = pack2(xp[(2 * j) << 12], xp[(2 * j + 1) << 12]);

    const unsigned sbase = (unsigned)__cvta_generic_to_shared(es);

    float best = FLT_MAX;
    int   bi   = 0;

    for (int ch = 0; ch < 4; ++ch) {
        __syncthreads();
        {   // cooperative load of 128 codes (8192 floats) + norms
            const float4* src = reinterpret_cast<const float4*>(emb) + ch * 2048;
            float4* dst = reinterpret_cast<float4*>(es);
#pragma unroll
            for (int i = 0; i < 8; ++i) dst[tid + i * 256] = src[tid + i * 256];
            if (tid < 128) en2s[tid] = g_en2[ch * 128 + tid];
        }
        __syncthreads();

#pragma unroll 2
        for (int e = 0; e < 128; ++e) {
            unsigned ad = sbase + e * (EMBED_DIM * 4);
            ull a0 = 0, a1 = 0;
#pragma unroll
            for (int j = 0; j < 16; ++j) {
                ull e01, e23;
                lds_v2_u64(e01, e23, ad + j * 16);
                a0 = fma2(xv[2 * j],     e01, a0);
                a1 = fma2(xv[2 * j + 1], e23, a1);
            }
            float2 sa = unpack2(add2(a0, a1));
            float dot = sa.x + sa.y;
            float d = fmaf(-2.0f, dot, en2s[e]);
            int ei = ch * 128 + e;
            bool c = d < best;
            best = c ? d : best;
            bi   = c ? ei : bi;
        }
    }

    // ---- Emit outputs ----
    float* out_main = dout + OFF_OUT;
    float* out_enc  = dout + OFF_ENC;

    // Coalesced zero of this block's 256 contiguous encodings rows (512 KB).
    // OFF_ENC is only 8-byte aligned -> float2.
    {
        float2* ez = reinterpret_cast<float2*>(out_enc + (size_t)tbase * NUM_EMBED);
        float2 z2 = make_float2(0.0f, 0.0f);
#pragma unroll 8
        for (int i = tid; i < 256 * NUM_EMBED / 2; i += 256) ez[i] = z2;
    }
    __syncthreads();
    out_enc[(size_t)(tbase + tid) * NUM_EMBED + bi] = 1.0f;

    atomicAdd(&g_counts[bi], 1.0f);

    const float* q  = emb + bi * EMBED_DIM;
    float* op       = out_main + ((size_t)n << 18) + hw;
    float* dwp      = g_dw + bi * EMBED_DIM;

    float lsum = 0.0f;
#pragma unroll
    for (int j = 0; j < 16; ++j) {
        float2 x0 = unpack2(xv[2 * j]);
        float2 x1 = unpack2(xv[2 * j + 1]);
        float q0 = q[4 * j], q1 = q[4 * j + 1], q2 = q[4 * j + 2], q3 = q[4 * j + 3];
        float d0 = q0 - x0.x, d1 = q1 - x0.y, d2 = q2 - x1.x, d3 = q3 - x1.y;
        op[(4 * j)     << 12] = q0;
        op[(4 * j + 1) << 12] = q1;
        op[(4 * j + 2) << 12] = q2;
        op[(4 * j + 3) << 12] = q3;
        lsum += d0 * d0 + d1 * d1 + d2 * d2 + d3 * d3;
        red_add_v4(dwp + 4 * j, x0.x, x0.y, x1.x, x1.y);
    }

    // block-reduce loss partial
    red[tid] = lsum;
    __syncthreads();
#pragma unroll
    for (int o = 128; o > 0; o >>= 1) {
        if (tid < o) red[tid] += red[tid + o];
        __syncthreads();
    }
    if (tid == 0) atomicAdd(&g_loss, red[0]);
}

// ============================================================
// Phase 2: EMA finalize + perplexity + loss. One block, 512 threads.
// ============================================================
__global__ void vq_phase2(const float* __restrict__ ema_cs,
                          const float* __restrict__ ema_w,
                          float* __restrict__ dout) {
    __shared__ float s[512];
    int e = threadIdx.x;

    float cnt = g_counts[e];
    float cl = ema_cs[e] * DECAY + ONE_MINUS_DECAY * cnt;

    s[e] = cl;
    __syncthreads();
    for (int o = 256; o > 0; o >>= 1) {
        if (e < o) s[e] += s[e + o];
        __syncthreads();
    }
    float k = s[0];
    __syncthreads();

    float cls = (cl + EPS) / (k + NUM_EMBED * EPS) * k;
    dout[OFF_CLUST + e] = cls;

    const float2* wp = reinterpret_cast<const float2*>(ema_w + e * EMBED_DIM);
    const float2* dp = reinterpret_cast<const float2*>(g_dw + e * EMBED_DIM);
    float2* ow = reinterpret_cast<float2*>(dout + OFF_EMAW + (size_t)e * EMBED_DIM);
    float2* oe = reinterpret_cast<float2*>(dout + OFF_NEMB + (size_t)e * EMBED_DIM);
#pragma unroll
    for (int j = 0; j < 32; ++j) {
        float2 w = wp[j];
        float2 d = dp[j];
        float w0 = w.x * DECAY + ONE_MINUS_DECAY * d.x;
        float w1 = w.y * DECAY + ONE_MINUS_DECAY * d.y;
        ow[j] = make_float2(w0, w1);
        oe[j] = make_float2(w0 / cls, w1 / cls);
    }

    float p = cnt * (1.0f / (float)N_TOKENS);
    float t = -p * logf(p + 1e-10f);
    s[e] = t;
    __syncthreads();
    for (int o = 256; o > 0; o >>= 1) {
        if (e < o) s[e] += s[e + o];
        __syncthreads();
    }
    if (e == 0) {
        dout[OFF_PERP] = expf(s[0]);
        dout[OFF_LOSS] = COMMIT_COST * (g_loss / 8388608.0f);
    }
}

// ============================================================
extern "C" void kernel_launch(void* const* d_in, const int* in_sizes, int n_in,
                              void* d_out, int out_size) {
    const float* x      = (const float*)d_in[0];
    const float* emb    = (const float*)d_in[1];
    const float* ema_w  = (const float*)d_in[2];
    const float* ema_cs = (const float*)d_in[3];
    float* dout = (float*)d_out;

    vq_phase0<<<64, 512>>>(emb);
    vq_phase1<<<256, 256>>>(x, emb, dout, 0);       // tokens [0, 65536)
    vq_phase1<<<256, 256>>>(x, emb, dout, 65536);   // tokens [65536, 131072)
    vq_phase2<<<1, 512>>>(ema_cs, ema_w, dout);
}

// round 9
// speedup vs baseline: 1.5474x; 1.1492x over previous
#include <cuda_runtime.h>
#include <cuda_bf16.h>
#include <cfloat>
#include <cstdint>

// Problem constants
#define NUM_EMBED 512
#define EMBED_DIM 64
#define N_TOKENS  131072            // 32 * 64 * 64
#define DECAY     0.99f
#define ONE_MINUS_DECAY 0.01f
#define EPS       1e-5f
#define COMMIT_COST 0.25f

// Output layout (float elements), tuple order:
// (loss[1], out[8388608], perplexity[1], encodings[131072*512],
//  new_embedding[512*64], cluster[512], new_ema_w[512*64])
#define OFF_LOSS   0
#define OFF_OUT    1
#define OFF_PERP   8388609
#define OFF_ENC    8388610
#define OFF_NEMB   75497474ll
#define OFF_CLUST  75530242ll
#define OFF_EMAW   75530754ll

// Scratch (no allocations allowed -> device globals).
// INVARIANT: g_counts/g_loss/g_dw are zero at kernel_launch entry.
// Zero-initialized at module load; phase2a/2b re-zero them after
// consuming, so the invariant holds across graph replays.
__device__ float               g_counts[NUM_EMBED];
__device__ __align__(16) float g_dw[NUM_EMBED * EMBED_DIM];
__device__ float               g_en2[NUM_EMBED];
__device__ float               g_cls[NUM_EMBED];
__device__ float               g_loss;

typedef unsigned long long ull;

// ---- f32x2 packed-math helpers (sm_100+; PTX-only) ----
__device__ __forceinline__ ull fma2(ull a, ull b, ull c) {
    ull d;
    asm("fma.rn.f32x2 %0, %1, %2, %3;" : "=l"(d) : "l"(a), "l"(b), "l"(c));
    return d;
}
__device__ __forceinline__ ull add2(ull a, ull b) {
    ull d;
    asm("add.rn.f32x2 %0, %1, %2;" : "=l"(d) : "l"(a), "l"(b));
    return d;
}
__device__ __forceinline__ ull pack2(float lo, float hi) {
    ull d;
    asm("mov.b64 %0, {%1, %2};" : "=l"(d) : "f"(lo), "f"(hi));
    return d;
}
__device__ __forceinline__ float2 unpack2(ull v) {
    float2 r;
    asm("mov.b64 {%0, %1}, %2;" : "=f"(r.x), "=f"(r.y) : "l"(v));
    return r;
}
__device__ __forceinline__ void lds_v2_u64(ull& a, ull& b, unsigned addr) {
    asm("ld.shared.v2.u64 {%0, %1}, [%2];" : "=l"(a), "=l"(b) : "r"(addr));
}
__device__ __forceinline__ void red_add_v4(float* p, float a, float b, float c, float d) {
    asm volatile("red.global.add.v4.f32 [%0], {%1,%2,%3,%4};"
                 :: "l"(p), "f"(a), "f"(b), "f"(c), "f"(d) : "memory");
}

// ============================================================
// Phase 0: ||e||^2 only. 1 block x 512 threads.
// NOTE: expression kept VERBATIM from the passing rounds — en2
// rounding is argmin-tie-critical; do not "improve" this.
// ============================================================
__global__ void vq_phase0(const float* __restrict__ emb) {
    int tid = threadIdx.x;
    const float2* ep = reinterpret_cast<const float2*>(emb + tid * EMBED_DIM);
    float s = 0.0f;
#pragma unroll
    for (int j = 0; j < 32; ++j) {
        float2 v = ep[j];
        s += v.x * v.x + v.y * v.y;
    }
    g_en2[tid] = s;
}

// ============================================================
// Phase 1: fused argmin + quantize + out + encodings + counts + dw + loss.
// 512 blocks x 256 threads, one token per thread.
// Distance inner loop kept VERBATIM (bit-exact) from the passing round.
// ============================================================
__global__ void __launch_bounds__(256, 2)
vq_phase1(const float* __restrict__ x,
          const float* __restrict__ emb,
          float* __restrict__ dout) {
    __shared__ float es[128 * EMBED_DIM];   // 32 KB code chunk
    __shared__ float en2s[128];
    __shared__ float red[256];

    const int tid   = threadIdx.x;
    const int tbase = blockIdx.x << 8;            // 256 tokens per block
    const int n     = tbase >> 12;                // batch index
    const int hw    = (tbase & 4095) + tid;       // spatial pos of this token

    float* out_main = dout + OFF_OUT;
    float* out_enc  = dout + OFF_ENC;

    // Coalesced zero of this block's 256 contiguous encodings rows (512 KB),
    // issued FIRST so the store drain overlaps the fma-bound distance loop.
    // OFF_ENC is only 8-byte aligned -> float2.
    {
        float2* ez = reinterpret_cast<float2*>(out_enc + (size_t)tbase * NUM_EMBED);
        float2 z2 = make_float2(0.0f, 0.0f);
#pragma unroll 8
        for (int i = tid; i < 256 * NUM_EMBED / 2; i += 256) ez[i] = z2;
    }

    const float* xp = x + ((size_t)n << 18) + hw; // n*64*4096 + hw

    // Load this token's 64 features, packed as f32x2 dim pairs.
    ull xv[32];
#pragma unroll
    for (int j = 0; j < 32; ++j)
        xv[j] = pack2(xp[(2 * j) << 12], xp[(2 * j + 1) << 12]);

    const unsigned sbase = (unsigned)__cvta_generic_to_shared(es);

    float best = FLT_MAX;
    int   bi   = 0;

    for (int ch = 0; ch < 4; ++ch) {
        __syncthreads();
        {   // cooperative load of 128 codes (8192 floats) + norms
            const float4* src = reinterpret_cast<const float4*>(emb) + ch * 2048;
            float4* dst = reinterpret_cast<float4*>(es);
#pragma unroll
            for (int i = 0; i < 8; ++i) dst[tid + i * 256] = src[tid + i * 256];
            if (tid < 128) en2s[tid] = g_en2[ch * 128 + tid];
        }
        __syncthreads();

#pragma unroll 2
        for (int e = 0; e < 128; ++e) {
            unsigned ad = sbase + e * (EMBED_DIM * 4);
            ull a0 = 0, a1 = 0;
#pragma unroll
            for (int j = 0; j < 16; ++j) {
                ull e01, e23;
                lds_v2_u64(e01, e23, ad + j * 16);
                a0 = fma2(xv[2 * j],     e01, a0);
                a1 = fma2(xv[2 * j + 1], e23, a1);
            }
            float2 sa = unpack2(add2(a0, a1));
            float dot = sa.x + sa.y;
            float d = fmaf(-2.0f, dot, en2s[e]);
            int ei = ch * 128 + e;
            bool c = d < best;
            best = c ? d : best;
            bi   = c ? ei : bi;
        }
    }

    // ---- Emit outputs ----
    out_enc[(size_t)(tbase + tid) * NUM_EMBED + bi] = 1.0f;
    atomicAdd(&g_counts[bi], 1.0f);

    const float* q  = emb + bi * EMBED_DIM;
    float* op       = out_main + ((size_t)n << 18) + hw;
    float* dwp      = g_dw + bi * EMBED_DIM;

    float lsum = 0.0f;
#pragma unroll
    for (int j = 0; j < 16; ++j) {
        float2 x0 = unpack2(xv[2 * j]);
        float2 x1 = unpack2(xv[2 * j + 1]);
        float q0 = q[4 * j], q1 = q[4 * j + 1], q2 = q[4 * j + 2], q3 = q[4 * j + 3];
        // mirror reference exactly: out = x + (q - x) in fp32 (no folding)
        float d0 = __fsub_rn(q0, x0.x);
        float d1 = __fsub_rn(q1, x0.y);
        float d2 = __fsub_rn(q2, x1.x);
        float d3 = __fsub_rn(q3, x1.y);
        op[(4 * j)     << 12] = __fadd_rn(x0.x, d0);
        op[(4 * j + 1) << 12] = __fadd_rn(x0.y, d1);
        op[(4 * j + 2) << 12] = __fadd_rn(x1.x, d2);
        op[(4 * j + 3) << 12] = __fadd_rn(x1.y, d3);
        lsum += d0 * d0 + d1 * d1 + d2 * d2 + d3 * d3;
        red_add_v4(dwp + 4 * j, x0.x, x0.y, x1.x, x1.y);
    }

    // block-reduce loss partial
    red[tid] = lsum;
    __syncthreads();
#pragma unroll
    for (int o = 128; o > 0; o >>= 1) {
        if (tid < o) red[tid] += red[tid + o];
        __syncthreads();
    }
    if (tid == 0) atomicAdd(&g_loss, red[0]);
}

// ============================================================
// Phase 2a: scalar finalize — cluster, k, perplexity, loss.
// One block, 512 threads. Re-zeros g_counts/g_loss after use.
// ============================================================
__global__ void vq_phase2a(const float* __restrict__ ema_cs,
                           float* __restrict__ dout) {
    __shared__ float s[512];
    int e = threadIdx.x;

    float cnt = g_counts[e];
    g_counts[e] = 0.0f;                       // recycle for next replay
    float cl = ema_cs[e] * DECAY + ONE_MINUS_DECAY * cnt;

    s[e] = cl;
    __syncthreads();
    for (int o = 256; o > 0; o >>= 1) {
        if (e < o) s[e] += s[e + o];
        __syncthreads();
    }
    float k = s[0];
    __syncthreads();

    float cls = (cl + EPS) / (k + NUM_EMBED * EPS) * k;
    dout[OFF_CLUST + e] = cls;
    g_cls[e] = cls;

    float p = cnt * (1.0f / (float)N_TOKENS);
    float t = -p * logf(p + 1e-10f);
    s[e] = t;
    __syncthreads();
    for (int o = 256; o > 0; o >>= 1) {
        if (e < o) s[e] += s[e + o];
        __syncthreads();
    }
    if (e == 0) {
        dout[OFF_PERP] = expf(s[0]);
        dout[OFF_LOSS] = COMMIT_COST * (g_loss / 8388608.0f);
        g_loss = 0.0f;                        // recycle
    }
}

// ============================================================
// Phase 2b: EMA rows, fully parallel. 64 blocks x 512 threads,
// one element each. Re-zeros g_dw after use.
// ============================================================
__global__ void vq_phase2b(const float* __restrict__ ema_w,
                           float* __restrict__ dout) {
    int gid = blockIdx.x * 512 + threadIdx.x;   // 0..32767
    int row = gid >> 6;                         // code index

    float d = g_dw[gid];
    g_dw[gid] = 0.0f;                           // recycle for next replay
    float w = ema_w[gid] * DECAY + ONE_MINUS_DECAY * d;
    dout[OFF_EMAW + gid] = w;
    dout[OFF_NEMB + gid] = w / g_cls[row];
}

// ============================================================
extern "C" void kernel_launch(void* const* d_in, const int* in_sizes, int n_in,
                              void* d_out, int out_size) {
    const float* x      = (const float*)d_in[0];
    const float* emb    = (const float*)d_in[1];
    const float* ema_w  = (const float*)d_in[2];
    const float* ema_cs = (const float*)d_in[3];
    float* dout = (float*)d_out;

    vq_phase0<<<1, 512>>>(emb);
    vq_phase1<<<512, 256>>>(x, emb, dout);
    vq_phase2a<<<1, 512>>>(ema_cs, dout);
    vq_phase2b<<<64, 512>>>(ema_w, dout);
}